// round 11
// baseline (speedup 1.0000x reference)
#include <cuda_runtime.h>
#include <cuda_fp16.h>
#include <cstdint>
#include <cstddef>

#define HW 4096
#define CD 64
// SCALE * log2(e): S' = logit*log2e, p = exp2(S')
#define PRESCALE 0.18033688011112042f
#define SW(o) ((o) ^ (((o) >> 3) & 0x70))

// denom[n][k] = sum_q exp(scale * Q[n,q,:].K[n,k,:])
__device__ float g_denom[4 * HW];

// fp16 images (swizzled 128B rows, ready for cp.async -> ldmatrix):
// Q: plain fp16, per (n, 128-row chunk): 16KB.
__device__ char g_Qb[(size_t)4 * 32 * 16384];
// K: prescaled by PRESCALE, split hi/lo: per chunk [hi 16KB][lo 16KB].
__device__ char g_Kb[(size_t)4 * 32 * 32768];
// Vt = (V/denom)^T: per chunk [vh: k-half0 8KB, k-half1 8KB][vl: same].
__device__ char g_Vb[(size_t)4 * 32 * 32768];

__device__ __forceinline__ uint32_t smem_u32(const void* p) {
    uint32_t a;
    asm("{ .reg .u64 t; cvta.to.shared.u64 t, %1; cvt.u32.u64 %0, t; }" : "=r"(a) : "l"(p));
    return a;
}

__device__ __forceinline__ void cpa16(uint32_t dst, const char* src) {
    asm volatile("cp.async.cg.shared.global [%0], [%1], 16;" :: "r"(dst), "l"(src) : "memory");
}
#define CP_COMMIT() asm volatile("cp.async.commit_group;" ::: "memory")
#define CP_WAIT0()  asm volatile("cp.async.wait_group 0;" ::: "memory")

// ldmatrix x4 from a 128B-row SW128 buffer: 16 rows x 16 fp16 cols.
__device__ __forceinline__ void ld4(uint32_t r[4], uint32_t base, int row0, int kbyte) {
    int l = threadIdx.x & 31;
    uint32_t o = (uint32_t)((row0 + (l & 15)) * 128 + kbyte + ((l >> 4) << 4));
    uint32_t a = base + SW(o);
    asm volatile("ldmatrix.sync.aligned.m8n8.x4.shared.b16 {%0,%1,%2,%3}, [%4];"
                 : "=r"(r[0]), "=r"(r[1]), "=r"(r[2]), "=r"(r[3]) : "r"(a));
}

__device__ __forceinline__ void mma16816(float c[4], const uint32_t a[4], uint32_t b0, uint32_t b1) {
    asm volatile(
        "mma.sync.aligned.m16n8k16.row.col.f32.f16.f16.f32 "
        "{%0,%1,%2,%3}, {%4,%5,%6,%7}, {%8,%9}, {%0,%1,%2,%3};"
        : "+f"(c[0]), "+f"(c[1]), "+f"(c[2]), "+f"(c[3])
        : "r"(a[0]), "r"(a[1]), "r"(a[2]), "r"(a[3]), "r"(b0), "r"(b1));
}

// ---------------------------------------------------------------------------
// Prep A: Q -> plain fp16; K -> PRESCALE*K split fp16 hi/lo. Zeroes g_denom.
// grid (64 slabs, N), 128 threads; slab = 64 rows.
// ---------------------------------------------------------------------------
__global__ void __launch_bounds__(128)
prep_qk(const float* __restrict__ Q, const float* __restrict__ K) {
    int tid = threadIdx.x;
    int s = blockIdx.x, n = blockIdx.y;
    int c = s >> 1, half = s & 1;
    size_t qgb = (size_t)(n * 32 + c) * 16384;
    size_t kgb = (size_t)(n * 32 + c) * 32768;
    const float* Qg = Q + ((size_t)n * HW + s * 64) * CD;
    const float* Kg = K + ((size_t)n * HW + s * 64) * CD;

    if (s < 32) g_denom[n * HW + s * 128 + tid] = 0.0f;

#pragma unroll
    for (int i = 0; i < 8; i++) {
        int lin4 = i * 128 + tid;
        int r  = lin4 >> 4;
        int c4 = (lin4 & 15) * 4;
        unsigned o = (half * 64 + r) * 128 + c4 * 2;
        unsigned sw = SW(o);
        {
            float4 v = *(const float4*)(Qg + r * CD + c4);
            __half2 h0 = __floats2half2_rn(v.x, v.y);
            __half2 h1 = __floats2half2_rn(v.z, v.w);
            *(unsigned*)(g_Qb + qgb + sw)     = *(unsigned*)&h0;
            *(unsigned*)(g_Qb + qgb + sw + 4) = *(unsigned*)&h1;
        }
        {
            float4 v = *(const float4*)(Kg + r * CD + c4);
            float x0 = v.x * PRESCALE, x1 = v.y * PRESCALE;
            float x2 = v.z * PRESCALE, x3 = v.w * PRESCALE;
            __half2 h0 = __floats2half2_rn(x0, x1);
            __half2 h1 = __floats2half2_rn(x2, x3);
            __half2 l0 = __floats2half2_rn(x0 - __low2float(h0), x1 - __high2float(h0));
            __half2 l1 = __floats2half2_rn(x2 - __low2float(h1), x3 - __high2float(h1));
            *(unsigned*)(g_Kb + kgb + sw)             = *(unsigned*)&h0;
            *(unsigned*)(g_Kb + kgb + sw + 4)         = *(unsigned*)&h1;
            *(unsigned*)(g_Kb + kgb + 16384 + sw)     = *(unsigned*)&l0;
            *(unsigned*)(g_Kb + kgb + 16384 + sw + 4) = *(unsigned*)&l1;
        }
    }
}

// ---------------------------------------------------------------------------
// Pass 1: denom. CTA = 64 k rows x quarter of q-range.
// A = K hi/lo (chunk-invariant frags), B = Q fp16 chunks (8KB, double-buffered).
// smem: KH 8KB + KL 8KB + 2 x Qbuf 8KB = 32KB; 128 threads, up to 4 CTAs/SM.
// exp via fp16x2 EX2 (errors wash out in the 4096-term denom sum).
// ---------------------------------------------------------------------------
#define Z1_KH 0
#define Z1_KL 8192
#define Z1_QB(b) (16384 + (b) * 8192)
#define P1_SMEM 32768

__device__ __forceinline__ void p1_issue_q(uint32_t sb, int b, int n, int cc) {
    int tid = threadIdx.x;
    const char* qs = g_Qb + (size_t)(n * 32 + (cc >> 1)) * 16384 + (cc & 1) * 8192;
    uint32_t d = sb + Z1_QB(b);
#pragma unroll
    for (int i = 0; i < 4; i++) {
        int o = (i * 128 + tid) * 16;
        cpa16(d + o, qs + o);
    }
}

__global__ void __launch_bounds__(128, 4)
pass1_denom() {
    extern __shared__ char smem[];
    uint32_t sb = smem_u32(smem);
    int tid = threadIdx.x, w = tid >> 5, l = tid & 31;
    int kt = blockIdx.x;   // 0..63: 64-row k tile
    int qs = blockIdx.y;   // 0..3: q quarter (16 chunks of 64 rows)
    int n  = blockIdx.z;

    {
        const char* khi = g_Kb + (size_t)(n * 32 + (kt >> 1)) * 32768 + (kt & 1) * 8192;
        const char* klo = khi + 16384;
#pragma unroll
        for (int i = 0; i < 4; i++) {
            int o = (i * 128 + tid) * 16;
            cpa16(sb + Z1_KH + o, khi + o);
            cpa16(sb + Z1_KL + o, klo + o);
        }
        p1_issue_q(sb, 0, n, qs * 16);
        CP_COMMIT();
    }

    uint32_t ah[4][4], al[4][4];
    float ps0 = 0.f, ps1 = 0.f;

    for (int j = 0; j < 16; j++) {
        int b = j & 1;
        CP_WAIT0();
        __syncthreads();
        if (j < 15) { p1_issue_q(sb, b ^ 1, n, qs * 16 + j + 1); CP_COMMIT(); }
        if (j == 0) {
#pragma unroll
            for (int ks = 0; ks < 4; ks++) {
                ld4(ah[ks], sb + Z1_KH, w * 16, ks * 32);
                ld4(al[ks], sb + Z1_KL, w * 16, ks * 32);
            }
        }

        uint32_t qb = sb + Z1_QB(b);
        float sacc[4][8];
#pragma unroll
        for (int t = 0; t < 4; t++)
#pragma unroll
            for (int u = 0; u < 8; u++) sacc[t][u] = 0.f;

#pragma unroll
        for (int ks = 0; ks < 4; ks++) {
            uint32_t bh[4][4];
#pragma unroll
            for (int ntp = 0; ntp < 4; ntp++) ld4(bh[ntp], qb, ntp * 16, ks * 32);
#pragma unroll
            for (int ntp = 0; ntp < 4; ntp++) mma16816(&sacc[ntp][0], ah[ks], bh[ntp][0], bh[ntp][2]);
#pragma unroll
            for (int ntp = 0; ntp < 4; ntp++) mma16816(&sacc[ntp][4], ah[ks], bh[ntp][1], bh[ntp][3]);
#pragma unroll
            for (int ntp = 0; ntp < 4; ntp++) mma16816(&sacc[ntp][0], al[ks], bh[ntp][0], bh[ntp][2]);
#pragma unroll
            for (int ntp = 0; ntp < 4; ntp++) mma16816(&sacc[ntp][4], al[ks], bh[ntp][1], bh[ntp][3]);
        }

#pragma unroll
        for (int ntp = 0; ntp < 4; ntp++) {
            __half2 e0 = h2exp2(__floats2half2_rn(sacc[ntp][0], sacc[ntp][1]));
            __half2 e1 = h2exp2(__floats2half2_rn(sacc[ntp][4], sacc[ntp][5]));
            __half2 e2 = h2exp2(__floats2half2_rn(sacc[ntp][2], sacc[ntp][3]));
            __half2 e3 = h2exp2(__floats2half2_rn(sacc[ntp][6], sacc[ntp][7]));
            ps0 += __low2float(e0) + __high2float(e0) + __low2float(e1) + __high2float(e1);
            ps1 += __low2float(e2) + __high2float(e2) + __low2float(e3) + __high2float(e3);
        }
    }

    ps0 += __shfl_xor_sync(0xFFFFFFFFu, ps0, 1);
    ps0 += __shfl_xor_sync(0xFFFFFFFFu, ps0, 2);
    ps1 += __shfl_xor_sync(0xFFFFFFFFu, ps1, 1);
    ps1 += __shfl_xor_sync(0xFFFFFFFFu, ps1, 2);
    if ((l & 3) == 0) {
        int r = l >> 2;
        atomicAdd(&g_denom[n * HW + kt * 64 + w * 16 + r],     ps0);
        atomicAdd(&g_denom[n * HW + kt * 64 + w * 16 + 8 + r], ps1);
    }
}

// ---------------------------------------------------------------------------
// Prep B: Vt = (V/denom)^T, fp16 split hi/lo. Also zeroes Out (for the
// atomicAdd epilogue of pass2). grid (64 slabs, N), 128 thr.
// ---------------------------------------------------------------------------
__global__ void __launch_bounds__(128)
prep_v(const float* __restrict__ V, float* __restrict__ Out) {
    __shared__ char sm[16384];   // [hi 8KB][lo 8KB] for one 64-k half
    int tid = threadIdx.x;
    int s = blockIdx.x, n = blockIdx.y;
    int c = s >> 1, h = s & 1;

    // zero Out: 1M floats over 32768 threads = 8 float4 each
    {
        size_t t = ((size_t)(n * 64 + s) * 128 + tid) * 8;
        float4 z = make_float4(0.f, 0.f, 0.f, 0.f);
#pragma unroll
        for (int i = 0; i < 8; i++) *(float4*)(Out + (t + i) * 4) = z;
    }

    const float* g = V + ((size_t)n * HW + s * 64) * CD;
    const float* dn = g_denom + n * HW + s * 64;
#pragma unroll
    for (int i = 0; i < 8; i++) {
        int lin4 = i * 128 + tid;
        int k  = lin4 >> 4;        // local 0..63
        int c4 = (lin4 & 15) * 4;
        float di = __frcp_rn(dn[k]);
        float4 v = *(const float4*)(g + k * CD + c4);
        float vv[4] = {v.x * di, v.y * di, v.z * di, v.w * di};
#pragma unroll
        for (int j = 0; j < 4; j++) {
            __half hb = __float2half_rn(vv[j]);
            __half lb = __float2half_rn(vv[j] - __half2float(hb));
            unsigned o = (c4 + j) * 128 + k * 2;
            unsigned sw = SW(o);
            *(__half*)(sm + sw) = hb;
            *(__half*)(sm + 8192 + sw) = lb;
        }
    }
    __syncthreads();

    size_t gbh = (size_t)(n * 32 + c) * 32768 + h * 8192;
    size_t gbl = gbh + 16384;
#pragma unroll
    for (int i = 0; i < 4; i++) {
        int o = (i * 128 + tid) * 16;
        *(float4*)(g_Vb + gbh + o) = *(const float4*)(sm + o);
        *(float4*)(g_Vb + gbl + o) = *(const float4*)(sm + 8192 + o);
    }
}

// ---------------------------------------------------------------------------
// Pass 2: CTA = 64 q rows x HALF the k range (32 chunks), 128 threads,
// 3 CTAs/SM, grid 512 -> ~3.5 CTAs/SM avg. Epilogue: atomicAdd into Out
// (exactly 2 contributors per element -> bit-deterministic).
// smem: Q 8KB + 2 x 32KB = 72KB.
// ---------------------------------------------------------------------------
#define Q_OFF 0
#define BUF(b) (8192 + (b) * 32768)   /* KH, KL=+8192, VH=+16384, VL=+24576 */
#define P2_SMEM 73728

__device__ __forceinline__ void p2_issue_kv(uint32_t sb, int b, int n, int cc) {
    int tid = threadIdx.x;
    size_t cb = (size_t)(n * 32 + (cc >> 1)) * 32768 + (cc & 1) * 8192;
    const char* khi = g_Kb + cb;
    const char* vhi = g_Vb + cb;
    uint32_t d = sb + BUF(b);
#pragma unroll
    for (int i = 0; i < 4; i++) {
        int o = (i * 128 + tid) * 16;
        cpa16(d + o,         khi + o);
        cpa16(d + 8192 + o,  khi + 16384 + o);
        cpa16(d + 16384 + o, vhi + o);
        cpa16(d + 24576 + o, vhi + 16384 + o);
    }
}

__global__ void __launch_bounds__(128, 3)
pass2_out(float* __restrict__ Out) {
    extern __shared__ char smem[];
    uint32_t sb = smem_u32(smem);
    int tid = threadIdx.x, w = tid >> 5, l = tid & 31;
    int qt = blockIdx.x, kh = blockIdx.y, n = blockIdx.z;
    int cc0 = kh * 32;

    {
        const char* qsrc = g_Qb + (size_t)(n * 32 + (qt >> 1)) * 16384 + (qt & 1) * 8192;
#pragma unroll
        for (int i = 0; i < 4; i++) {
            int o = (i * 128 + tid) * 16;
            cpa16(sb + Q_OFF + o, qsrc + o);
        }
        p2_issue_kv(sb, 0, n, cc0);
        CP_COMMIT();
    }

    float oacc[8][4];
#pragma unroll
    for (int i = 0; i < 8; i++)
#pragma unroll
        for (int j = 0; j < 4; j++) oacc[i][j] = 0.f;

    uint32_t qh[4][4];

    for (int j = 0; j < 32; j++) {
        int b = j & 1;
        CP_WAIT0();
        __syncthreads();
        if (j < 31) { p2_issue_kv(sb, b ^ 1, n, cc0 + j + 1); CP_COMMIT(); }
        if (j == 0) {
#pragma unroll
            for (int ks = 0; ks < 4; ks++) ld4(qh[ks], sb + Q_OFF, w * 16, ks * 32);
        }

        uint32_t kb = sb + BUF(b);
        uint32_t vb = kb + 16384;

        // --- S' = Q.(Kh + Kl)^T over 64 k cols (logits*log2e) ---
        float sacc[4][8];
#pragma unroll
        for (int t = 0; t < 4; t++)
#pragma unroll
            for (int u = 0; u < 8; u++) sacc[t][u] = 0.f;

#pragma unroll
        for (int ks = 0; ks < 4; ks++) {
            uint32_t bh[4][4], bl[4][4];
#pragma unroll
            for (int ntp = 0; ntp < 4; ntp++) {
                ld4(bh[ntp], kb, ntp * 16, ks * 32);
                ld4(bl[ntp], kb + 8192, ntp * 16, ks * 32);
            }
#pragma unroll
            for (int ntp = 0; ntp < 4; ntp++) mma16816(&sacc[ntp][0], qh[ks], bh[ntp][0], bh[ntp][2]);
#pragma unroll
            for (int ntp = 0; ntp < 4; ntp++) mma16816(&sacc[ntp][4], qh[ks], bh[ntp][1], bh[ntp][3]);
#pragma unroll
            for (int ntp = 0; ntp < 4; ntp++) mma16816(&sacc[ntp][0], qh[ks], bl[ntp][0], bl[ntp][2]);
#pragma unroll
            for (int ntp = 0; ntp < 4; ntp++) mma16816(&sacc[ntp][4], qh[ks], bl[ntp][1], bl[ntp][3]);
        }

        // --- P = exp2(S') as fp16 A-fragments (fp32 EX2 for precision) ---
        uint32_t ph[4][4];
#pragma unroll
        for (int ntp = 0; ntp < 4; ntp++) {
            __half2 h;
            h = __floats2half2_rn(exp2f(sacc[ntp][0]), exp2f(sacc[ntp][1])); ph[ntp][0] = *(uint32_t*)&h;
            h = __floats2half2_rn(exp2f(sacc[ntp][2]), exp2f(sacc[ntp][3])); ph[ntp][1] = *(uint32_t*)&h;
            h = __floats2half2_rn(exp2f(sacc[ntp][4]), exp2f(sacc[ntp][5])); ph[ntp][2] = *(uint32_t*)&h;
            h = __floats2half2_rn(exp2f(sacc[ntp][6]), exp2f(sacc[ntp][7])); ph[ntp][3] = *(uint32_t*)&h;
        }

        // --- acc += P.(Vh + Vl)' ---
#pragma unroll
        for (int ks = 0; ks < 4; ks++) {
            uint32_t vh[4][4], vl[4][4];
#pragma unroll
            for (int cp = 0; cp < 4; cp++) {
                ld4(vh[cp], vb, cp * 16, ks * 32);
                ld4(vl[cp], vb + 8192, cp * 16, ks * 32);
            }
#pragma unroll
            for (int cp = 0; cp < 4; cp++) mma16816(oacc[2 * cp],     ph[ks], vh[cp][0], vh[cp][2]);
#pragma unroll
            for (int cp = 0; cp < 4; cp++) mma16816(oacc[2 * cp + 1], ph[ks], vh[cp][1], vh[cp][3]);
#pragma unroll
            for (int cp = 0; cp < 4; cp++) mma16816(oacc[2 * cp],     ph[ks], vl[cp][0], vl[cp][2]);
#pragma unroll
            for (int cp = 0; cp < 4; cp++) mma16816(oacc[2 * cp + 1], ph[ks], vl[cp][1], vl[cp][3]);
        }
    }

    // --- epilogue: atomicAdd partial O (2 contributors/element, deterministic) ---
    {
        int qr = qt * 64 + w * 16 + (l >> 2);
        float* o0 = Out + ((size_t)n * HW + qr) * CD;
        float* o1 = o0 + 8 * CD;
#pragma unroll
        for (int nt = 0; nt < 8; nt++) {
            int c0 = nt * 8 + 2 * (l & 3);
            atomicAdd(o0 + c0,     oacc[nt][0]);
            atomicAdd(o0 + c0 + 1, oacc[nt][1]);
            atomicAdd(o1 + c0,     oacc[nt][2]);
            atomicAdd(o1 + c0 + 1, oacc[nt][3]);
        }
    }
}

// ---------------------------------------------------------------------------
extern "C" void kernel_launch(void* const* d_in, const int* in_sizes, int n_in,
                              void* d_out, int out_size) {
    const float* Q = (const float*)d_in[0];
    const float* K = (const float*)d_in[1];
    const float* V = (const float*)d_in[2];
    float* Out = (float*)d_out;
    const int N = in_sizes[0] / (HW * CD);  // = 4

    cudaFuncSetAttribute(pass1_denom, cudaFuncAttributeMaxDynamicSharedMemorySize, P1_SMEM);
    cudaFuncSetAttribute(pass2_out,   cudaFuncAttributeMaxDynamicSharedMemorySize, P2_SMEM);

    prep_qk<<<dim3(64, N), 128>>>(Q, K);
    pass1_denom<<<dim3(64, 4, N), 128, P1_SMEM>>>();
    prep_v<<<dim3(64, N), 128>>>(V, Out);
    pass2_out<<<dim3(64, 2, N), 128, P2_SMEM>>>(Out);
}

// round 12
// speedup vs baseline: 1.6514x; 1.6514x over previous
#include <cuda_runtime.h>
#include <cuda_fp16.h>
#include <cstdint>
#include <cstddef>

#define HW 4096
#define CD 64
// SCALE * log2(e): S' = logit*log2e, p = exp2(S')
#define PRESCALE 0.18033688011112042f
#define SW(o) ((o) ^ (((o) >> 3) & 0x70))

// denom[n][k] = sum_q exp(scale * Q[n,q,:].K[n,k,:])
__device__ float g_denom[4 * HW];

// fp16 images (swizzled 128B rows, ready for cp.async -> ldmatrix):
// Q: plain fp16, per (n, 128-row chunk): 16KB.
__device__ char g_Qb[(size_t)4 * 32 * 16384];
// K: prescaled by PRESCALE, plain fp16: per chunk 16KB.
__device__ char g_Kb[(size_t)4 * 32 * 16384];
// Vt = (V/denom)^T fp16: per chunk [k-half0 8KB][k-half1 8KB].
__device__ char g_Vb[(size_t)4 * 32 * 16384];

__device__ __forceinline__ uint32_t smem_u32(const void* p) {
    uint32_t a;
    asm("{ .reg .u64 t; cvta.to.shared.u64 t, %1; cvt.u32.u64 %0, t; }" : "=r"(a) : "l"(p));
    return a;
}

__device__ __forceinline__ void cpa16(uint32_t dst, const char* src) {
    asm volatile("cp.async.cg.shared.global [%0], [%1], 16;" :: "r"(dst), "l"(src) : "memory");
}
#define CP_COMMIT() asm volatile("cp.async.commit_group;" ::: "memory")
#define CP_WAIT0()  asm volatile("cp.async.wait_group 0;" ::: "memory")

// ldmatrix x4 from a 128B-row SW128 buffer: 16 rows x 16 fp16 cols.
__device__ __forceinline__ void ld4(uint32_t r[4], uint32_t base, int row0, int kbyte) {
    int l = threadIdx.x & 31;
    uint32_t o = (uint32_t)((row0 + (l & 15)) * 128 + kbyte + ((l >> 4) << 4));
    uint32_t a = base + SW(o);
    asm volatile("ldmatrix.sync.aligned.m8n8.x4.shared.b16 {%0,%1,%2,%3}, [%4];"
                 : "=r"(r[0]), "=r"(r[1]), "=r"(r[2]), "=r"(r[3]) : "r"(a));
}

__device__ __forceinline__ void mma16816(float c[4], const uint32_t a[4], uint32_t b0, uint32_t b1) {
    asm volatile(
        "mma.sync.aligned.m16n8k16.row.col.f32.f16.f16.f32 "
        "{%0,%1,%2,%3}, {%4,%5,%6,%7}, {%8,%9}, {%0,%1,%2,%3};"
        : "+f"(c[0]), "+f"(c[1]), "+f"(c[2]), "+f"(c[3])
        : "r"(a[0]), "r"(a[1]), "r"(a[2]), "r"(a[3]), "r"(b0), "r"(b1));
}

// ---------------------------------------------------------------------------
// Prep A: Q -> plain fp16; K -> PRESCALE*K plain fp16. Zeroes g_denom.
// grid (64 slabs, N), 128 threads; slab = 64 rows.
// ---------------------------------------------------------------------------
__global__ void __launch_bounds__(128)
prep_qk(const float* __restrict__ Q, const float* __restrict__ K) {
    int tid = threadIdx.x;
    int s = blockIdx.x, n = blockIdx.y;
    int c = s >> 1, half = s & 1;
    size_t gb = (size_t)(n * 32 + c) * 16384;
    const float* Qg = Q + ((size_t)n * HW + s * 64) * CD;
    const float* Kg = K + ((size_t)n * HW + s * 64) * CD;

    if (s < 32) g_denom[n * HW + s * 128 + tid] = 0.0f;

#pragma unroll
    for (int i = 0; i < 8; i++) {
        int lin4 = i * 128 + tid;
        int r  = lin4 >> 4;
        int c4 = (lin4 & 15) * 4;
        unsigned o = (half * 64 + r) * 128 + c4 * 2;
        unsigned sw = SW(o);
        {
            float4 v = *(const float4*)(Qg + r * CD + c4);
            __half2 h0 = __floats2half2_rn(v.x, v.y);
            __half2 h1 = __floats2half2_rn(v.z, v.w);
            *(unsigned*)(g_Qb + gb + sw)     = *(unsigned*)&h0;
            *(unsigned*)(g_Qb + gb + sw + 4) = *(unsigned*)&h1;
        }
        {
            float4 v = *(const float4*)(Kg + r * CD + c4);
            __half2 h0 = __floats2half2_rn(v.x * PRESCALE, v.y * PRESCALE);
            __half2 h1 = __floats2half2_rn(v.z * PRESCALE, v.w * PRESCALE);
            *(unsigned*)(g_Kb + gb + sw)     = *(unsigned*)&h0;
            *(unsigned*)(g_Kb + gb + sw + 4) = *(unsigned*)&h1;
        }
    }
}

// ---------------------------------------------------------------------------
// Pass 1: denom. CTA = 64 k rows x quarter of q-range.
// A = K (chunk-invariant frags), B = Q fp16 chunks (8KB, double-buffered).
// smem: K 8KB + 2 x Qbuf 8KB = 24KB; 128 threads, 4 CTAs/SM.
// ---------------------------------------------------------------------------
#define Z1_K 0
#define Z1_QB(b) (8192 + (b) * 8192)
#define P1_SMEM 24576

__device__ __forceinline__ void p1_issue_q(uint32_t sb, int b, int n, int cc) {
    int tid = threadIdx.x;
    const char* qs = g_Qb + (size_t)(n * 32 + (cc >> 1)) * 16384 + (cc & 1) * 8192;
    uint32_t d = sb + Z1_QB(b);
#pragma unroll
    for (int i = 0; i < 4; i++) {
        int o = (i * 128 + tid) * 16;
        cpa16(d + o, qs + o);
    }
}

__global__ void __launch_bounds__(128, 4)
pass1_denom() {
    extern __shared__ char smem[];
    uint32_t sb = smem_u32(smem);
    int tid = threadIdx.x, w = tid >> 5, l = tid & 31;
    int kt = blockIdx.x;   // 0..63: 64-row k tile
    int qs = blockIdx.y;   // 0..3: q quarter (16 chunks of 64 rows)
    int n  = blockIdx.z;

    {
        const char* ksrc = g_Kb + (size_t)(n * 32 + (kt >> 1)) * 16384 + (kt & 1) * 8192;
#pragma unroll
        for (int i = 0; i < 4; i++) {
            int o = (i * 128 + tid) * 16;
            cpa16(sb + Z1_K + o, ksrc + o);
        }
        p1_issue_q(sb, 0, n, qs * 16);
        CP_COMMIT();
    }

    uint32_t ah[4][4];
    float ps0 = 0.f, ps1 = 0.f;

    for (int j = 0; j < 16; j++) {
        int b = j & 1;
        CP_WAIT0();
        __syncthreads();
        if (j < 15) { p1_issue_q(sb, b ^ 1, n, qs * 16 + j + 1); CP_COMMIT(); }
        if (j == 0) {
#pragma unroll
            for (int ks = 0; ks < 4; ks++) ld4(ah[ks], sb + Z1_K, w * 16, ks * 32);
        }

        uint32_t qb = sb + Z1_QB(b);
        float sacc[4][8];
#pragma unroll
        for (int t = 0; t < 4; t++)
#pragma unroll
            for (int u = 0; u < 8; u++) sacc[t][u] = 0.f;

#pragma unroll
        for (int ks = 0; ks < 4; ks++) {
            uint32_t bh[4][4];
#pragma unroll
            for (int ntp = 0; ntp < 4; ntp++) ld4(bh[ntp], qb, ntp * 16, ks * 32);
#pragma unroll
            for (int ntp = 0; ntp < 4; ntp++) mma16816(&sacc[ntp][0], ah[ks], bh[ntp][0], bh[ntp][2]);
#pragma unroll
            for (int ntp = 0; ntp < 4; ntp++) mma16816(&sacc[ntp][4], ah[ks], bh[ntp][1], bh[ntp][3]);
        }

#pragma unroll
        for (int ntp = 0; ntp < 4; ntp++) {
            __half2 e0 = h2exp2(__floats2half2_rn(sacc[ntp][0], sacc[ntp][1]));
            __half2 e1 = h2exp2(__floats2half2_rn(sacc[ntp][4], sacc[ntp][5]));
            __half2 e2 = h2exp2(__floats2half2_rn(sacc[ntp][2], sacc[ntp][3]));
            __half2 e3 = h2exp2(__floats2half2_rn(sacc[ntp][6], sacc[ntp][7]));
            ps0 += __low2float(e0) + __high2float(e0) + __low2float(e1) + __high2float(e1);
            ps1 += __low2float(e2) + __high2float(e2) + __low2float(e3) + __high2float(e3);
        }
    }

    ps0 += __shfl_xor_sync(0xFFFFFFFFu, ps0, 1);
    ps0 += __shfl_xor_sync(0xFFFFFFFFu, ps0, 2);
    ps1 += __shfl_xor_sync(0xFFFFFFFFu, ps1, 1);
    ps1 += __shfl_xor_sync(0xFFFFFFFFu, ps1, 2);
    if ((l & 3) == 0) {
        int r = l >> 2;
        atomicAdd(&g_denom[n * HW + kt * 64 + w * 16 + r],     ps0);
        atomicAdd(&g_denom[n * HW + kt * 64 + w * 16 + 8 + r], ps1);
    }
}

// ---------------------------------------------------------------------------
// Prep B: Vt = (V/denom)^T, plain fp16. grid (64 slabs, N), 128 thr.
// ---------------------------------------------------------------------------
__global__ void __launch_bounds__(128)
prep_v(const float* __restrict__ V) {
    __shared__ char sm[8192];   // one 64-k half: 64 c-rows x 128B
    int tid = threadIdx.x;
    int s = blockIdx.x, n = blockIdx.y;
    int c = s >> 1, h = s & 1;

    const float* g = V + ((size_t)n * HW + s * 64) * CD;
    const float* dn = g_denom + n * HW + s * 64;
#pragma unroll
    for (int i = 0; i < 8; i++) {
        int lin4 = i * 128 + tid;
        int k  = lin4 >> 4;        // local 0..63
        int c4 = (lin4 & 15) * 4;
        float di = __frcp_rn(dn[k]);
        float4 v = *(const float4*)(g + k * CD + c4);
        float vv[4] = {v.x * di, v.y * di, v.z * di, v.w * di};
#pragma unroll
        for (int j = 0; j < 4; j++) {
            unsigned o = (c4 + j) * 128 + k * 2;
            *(__half*)(sm + SW(o)) = __float2half_rn(vv[j]);
        }
    }
    __syncthreads();

    size_t gb = (size_t)(n * 32 + c) * 16384 + h * 8192;
#pragma unroll
    for (int i = 0; i < 4; i++) {
        int o = (i * 128 + tid) * 16;
        *(float4*)(g_Vb + gb + o) = *(const float4*)(sm + o);
    }
}

// ---------------------------------------------------------------------------
// Pass 2: CTA = 64 q rows, 128 threads, 4 CTAs/SM. 64 k-chunks of 64 rows,
// double-buffered K+Vt. Plain fp16: S = Q.K^T; PV = P.Vt'.
// smem: Q 8KB + 2 x (K 8KB + Vt 8KB) = 40KB.
// ---------------------------------------------------------------------------
#define Q_OFF 0
#define BUF(b) (8192 + (b) * 16384)   /* K, V=+8192 */
#define P2_SMEM 40960

__device__ __forceinline__ void p2_issue_kv(uint32_t sb, int b, int n, int cc) {
    int tid = threadIdx.x;
    size_t cb = (size_t)(n * 32 + (cc >> 1)) * 16384 + (cc & 1) * 8192;
    const char* ksrc = g_Kb + cb;
    const char* vsrc = g_Vb + cb;
    uint32_t d = sb + BUF(b);
#pragma unroll
    for (int i = 0; i < 4; i++) {
        int o = (i * 128 + tid) * 16;
        cpa16(d + o,        ksrc + o);
        cpa16(d + 8192 + o, vsrc + o);
    }
}

__global__ void __launch_bounds__(128, 4)
pass2_out(float* __restrict__ Out) {
    extern __shared__ char smem[];
    uint32_t sb = smem_u32(smem);
    int tid = threadIdx.x, w = tid >> 5, l = tid & 31;
    int qt = blockIdx.x, n = blockIdx.y;

    {
        const char* qsrc = g_Qb + (size_t)(n * 32 + (qt >> 1)) * 16384 + (qt & 1) * 8192;
#pragma unroll
        for (int i = 0; i < 4; i++) {
            int o = (i * 128 + tid) * 16;
            cpa16(sb + Q_OFF + o, qsrc + o);
        }
        p2_issue_kv(sb, 0, n, 0);
        CP_COMMIT();
    }

    float oacc[8][4];
#pragma unroll
    for (int i = 0; i < 8; i++)
#pragma unroll
        for (int j = 0; j < 4; j++) oacc[i][j] = 0.f;

    uint32_t qh[4][4];

    for (int j = 0; j < 64; j++) {
        int b = j & 1;
        CP_WAIT0();
        __syncthreads();
        if (j < 63) { p2_issue_kv(sb, b ^ 1, n, j + 1); CP_COMMIT(); }
        if (j == 0) {
#pragma unroll
            for (int ks = 0; ks < 4; ks++) ld4(qh[ks], sb + Q_OFF, w * 16, ks * 32);
        }

        uint32_t kb = sb + BUF(b);
        uint32_t vb = kb + 8192;

        // --- S' = Q.K^T over 64 k cols (logits*log2e) ---
        float sacc[4][8];
#pragma unroll
        for (int t = 0; t < 4; t++)
#pragma unroll
            for (int u = 0; u < 8; u++) sacc[t][u] = 0.f;

#pragma unroll
        for (int ks = 0; ks < 4; ks++) {
            uint32_t bh[4][4];
#pragma unroll
            for (int ntp = 0; ntp < 4; ntp++) ld4(bh[ntp], kb, ntp * 16, ks * 32);
#pragma unroll
            for (int ntp = 0; ntp < 4; ntp++) mma16816(&sacc[ntp][0], qh[ks], bh[ntp][0], bh[ntp][2]);
#pragma unroll
            for (int ntp = 0; ntp < 4; ntp++) mma16816(&sacc[ntp][4], qh[ks], bh[ntp][1], bh[ntp][3]);
        }

        // --- P = exp2(S') as fp16 A-fragments (fp32 EX2) ---
        uint32_t ph[4][4];
#pragma unroll
        for (int ntp = 0; ntp < 4; ntp++) {
            __half2 h;
            h = __floats2half2_rn(exp2f(sacc[ntp][0]), exp2f(sacc[ntp][1])); ph[ntp][0] = *(uint32_t*)&h;
            h = __floats2half2_rn(exp2f(sacc[ntp][2]), exp2f(sacc[ntp][3])); ph[ntp][1] = *(uint32_t*)&h;
            h = __floats2half2_rn(exp2f(sacc[ntp][4]), exp2f(sacc[ntp][5])); ph[ntp][2] = *(uint32_t*)&h;
            h = __floats2half2_rn(exp2f(sacc[ntp][6]), exp2f(sacc[ntp][7])); ph[ntp][3] = *(uint32_t*)&h;
        }

        // --- acc += P.Vt' ---
#pragma unroll
        for (int ks = 0; ks < 4; ks++) {
            uint32_t vh[4][4];
#pragma unroll
            for (int cp = 0; cp < 4; cp++) ld4(vh[cp], vb, cp * 16, ks * 32);
#pragma unroll
            for (int cp = 0; cp < 4; cp++) mma16816(oacc[2 * cp],     ph[ks], vh[cp][0], vh[cp][2]);
#pragma unroll
            for (int cp = 0; cp < 4; cp++) mma16816(oacc[2 * cp + 1], ph[ks], vh[cp][1], vh[cp][3]);
        }
    }

    // --- epilogue: direct stores ---
    {
        int qr = qt * 64 + w * 16 + (l >> 2);
        float* o0 = Out + ((size_t)n * HW + qr) * CD;
        float* o1 = o0 + 8 * CD;
#pragma unroll
        for (int nt = 0; nt < 8; nt++) {
            int c0 = nt * 8 + 2 * (l & 3);
            *(float2*)(o0 + c0) = make_float2(oacc[nt][0], oacc[nt][1]);
            *(float2*)(o1 + c0) = make_float2(oacc[nt][2], oacc[nt][3]);
        }
    }
}

// ---------------------------------------------------------------------------
extern "C" void kernel_launch(void* const* d_in, const int* in_sizes, int n_in,
                              void* d_out, int out_size) {
    const float* Q = (const float*)d_in[0];
    const float* K = (const float*)d_in[1];
    const float* V = (const float*)d_in[2];
    float* Out = (float*)d_out;
    const int N = in_sizes[0] / (HW * CD);  // = 4

    cudaFuncSetAttribute(pass1_denom, cudaFuncAttributeMaxDynamicSharedMemorySize, P1_SMEM);
    cudaFuncSetAttribute(pass2_out,   cudaFuncAttributeMaxDynamicSharedMemorySize, P2_SMEM);

    prep_qk<<<dim3(64, N), 128>>>(Q, K);
    pass1_denom<<<dim3(64, 4, N), 128, P1_SMEM>>>();
    prep_v<<<dim3(64, N), 128>>>(V);
    pass2_out<<<dim3(64, N), 128, P2_SMEM>>>(Out);
}

// round 13
// speedup vs baseline: 1.7530x; 1.0615x over previous
#include <cuda_runtime.h>
#include <cuda_fp16.h>
#include <cstdint>
#include <cstddef>

#define HW 4096
#define CD 64
// SCALE * log2(e): S' = logit*log2e, p = exp2(S')
#define PRESCALE 0.18033688011112042f
#define SW(o) ((o) ^ (((o) >> 3) & 0x70))

__device__ float g_denom[4 * HW];

// fp16 images (swizzled 128B rows): Q plain; K prescaled; Vt = (V/denom)^T.
__device__ char g_Qb[(size_t)4 * 32 * 16384];
__device__ char g_Kb[(size_t)4 * 32 * 16384];
__device__ char g_Vb[(size_t)4 * 32 * 16384];

__device__ __forceinline__ uint32_t smem_u32(const void* p) {
    uint32_t a;
    asm("{ .reg .u64 t; cvta.to.shared.u64 t, %1; cvt.u32.u64 %0, t; }" : "=r"(a) : "l"(p));
    return a;
}
__device__ __forceinline__ void cpa16(uint32_t dst, const char* src) {
    asm volatile("cp.async.cg.shared.global [%0], [%1], 16;" :: "r"(dst), "l"(src) : "memory");
}
#define CP_COMMIT() asm volatile("cp.async.commit_group;" ::: "memory")
#define CP_WAIT0()  asm volatile("cp.async.wait_group 0;" ::: "memory")
#define CP_WAIT1()  asm volatile("cp.async.wait_group 1;" ::: "memory")

__device__ __forceinline__ void ld4a(uint32_t r[4], uint32_t a) {
    asm volatile("ldmatrix.sync.aligned.m8n8.x4.shared.b16 {%0,%1,%2,%3}, [%4];"
                 : "=r"(r[0]), "=r"(r[1]), "=r"(r[2]), "=r"(r[3]) : "r"(a));
}
__device__ __forceinline__ void mma16816(float c[4], const uint32_t a[4], uint32_t b0, uint32_t b1) {
    asm volatile(
        "mma.sync.aligned.m16n8k16.row.col.f32.f16.f16.f32 "
        "{%0,%1,%2,%3}, {%4,%5,%6,%7}, {%8,%9}, {%0,%1,%2,%3};"
        : "+f"(c[0]), "+f"(c[1]), "+f"(c[2]), "+f"(c[3])
        : "r"(a[0]), "r"(a[1]), "r"(a[2]), "r"(a[3]), "r"(b0), "r"(b1));
}
__device__ __forceinline__ float ex2(float x) {
    float y; asm("ex2.approx.ftz.f32 %0, %1;" : "=f"(y) : "f"(x)); return y;
}

// 64x64 fp16 GEMM block: sacc[ntp][..] += A(16 rows/warp) x B(64 cols).
// Addresses: base + row0*128 + t128 + cx[ks]  (swizzle pre-folded into cx).
__device__ __forceinline__ void mma_block(float (&sacc)[4][8], const uint32_t (&ah)[4][4],
                                          uint32_t bbase, uint32_t t128, const uint32_t (&cx)[4]) {
#pragma unroll
    for (int t = 0; t < 4; t++)
#pragma unroll
        for (int u = 0; u < 8; u++) sacc[t][u] = 0.f;
#pragma unroll
    for (int ks = 0; ks < 4; ks++) {
        uint32_t bh[4][4];
#pragma unroll
        for (int ntp = 0; ntp < 4; ntp++) ld4a(bh[ntp], bbase + ntp * 2048 + t128 + cx[ks]);
#pragma unroll
        for (int ntp = 0; ntp < 4; ntp++) mma16816(&sacc[ntp][0], ah[ks], bh[ntp][0], bh[ntp][2]);
#pragma unroll
        for (int ntp = 0; ntp < 4; ntp++) mma16816(&sacc[ntp][4], ah[ks], bh[ntp][1], bh[ntp][3]);
    }
}

__device__ __forceinline__ void exp_block(uint32_t (&ph)[4][4], const float (&sacc)[4][8]) {
#pragma unroll
    for (int ntp = 0; ntp < 4; ntp++) {
        __half2 h;
        h = __floats2half2_rn(ex2(sacc[ntp][0]), ex2(sacc[ntp][1])); ph[ntp][0] = *(uint32_t*)&h;
        h = __floats2half2_rn(ex2(sacc[ntp][2]), ex2(sacc[ntp][3])); ph[ntp][1] = *(uint32_t*)&h;
        h = __floats2half2_rn(ex2(sacc[ntp][4]), ex2(sacc[ntp][5])); ph[ntp][2] = *(uint32_t*)&h;
        h = __floats2half2_rn(ex2(sacc[ntp][6]), ex2(sacc[ntp][7])); ph[ntp][3] = *(uint32_t*)&h;
    }
}

__device__ __forceinline__ void pv_block(float (&oacc)[8][4], const uint32_t (&ph)[4][4],
                                         uint32_t vbase, uint32_t t128, const uint32_t (&cx)[4]) {
#pragma unroll
    for (int ks = 0; ks < 4; ks++) {
        uint32_t vh[4][4];
#pragma unroll
        for (int cp = 0; cp < 4; cp++) ld4a(vh[cp], vbase + cp * 2048 + t128 + cx[ks]);
#pragma unroll
        for (int cp = 0; cp < 4; cp++) mma16816(oacc[2 * cp],     ph[ks], vh[cp][0], vh[cp][2]);
#pragma unroll
        for (int cp = 0; cp < 4; cp++) mma16816(oacc[2 * cp + 1], ph[ks], vh[cp][1], vh[cp][3]);
    }
}

// ---------------------------------------------------------------------------
// Prep A: Q -> fp16; K -> PRESCALE*K fp16. Zeroes g_denom.
// ---------------------------------------------------------------------------
__global__ void __launch_bounds__(128)
prep_qk(const float* __restrict__ Q, const float* __restrict__ K) {
    int tid = threadIdx.x;
    int s = blockIdx.x, n = blockIdx.y;
    int c = s >> 1, half = s & 1;
    size_t gb = (size_t)(n * 32 + c) * 16384;
    const float* Qg = Q + ((size_t)n * HW + s * 64) * CD;
    const float* Kg = K + ((size_t)n * HW + s * 64) * CD;

    if (s < 32) g_denom[n * HW + s * 128 + tid] = 0.0f;

#pragma unroll
    for (int i = 0; i < 8; i++) {
        int lin4 = i * 128 + tid;
        int r  = lin4 >> 4;
        int c4 = (lin4 & 15) * 4;
        unsigned o = (half * 64 + r) * 128 + c4 * 2;
        unsigned sw = SW(o);
        {
            float4 v = *(const float4*)(Qg + r * CD + c4);
            __half2 h0 = __floats2half2_rn(v.x, v.y);
            __half2 h1 = __floats2half2_rn(v.z, v.w);
            *(unsigned*)(g_Qb + gb + sw)     = *(unsigned*)&h0;
            *(unsigned*)(g_Qb + gb + sw + 4) = *(unsigned*)&h1;
        }
        {
            float4 v = *(const float4*)(Kg + r * CD + c4);
            __half2 h0 = __floats2half2_rn(v.x * PRESCALE, v.y * PRESCALE);
            __half2 h1 = __floats2half2_rn(v.z * PRESCALE, v.w * PRESCALE);
            *(unsigned*)(g_Kb + gb + sw)     = *(unsigned*)&h0;
            *(unsigned*)(g_Kb + gb + sw + 4) = *(unsigned*)&h1;
        }
    }
}

// ---------------------------------------------------------------------------
// Pass 1: denom. CTA = 64 k rows x quarter q-range. Q triple-buffered ring;
// S(j+1) overlapped with exp-sum(j). smem: K 8KB + 3 x Q 8KB = 32KB.
// ---------------------------------------------------------------------------
#define Z1_K 0
#define QBUF(b) (8192 + (b) * 8192)
#define P1_SMEM 32768

__device__ __forceinline__ void p1_issue_q(uint32_t sb, int bi, int n, int cc) {
    int tid = threadIdx.x;
    const char* qs = g_Qb + (size_t)(n * 32 + (cc >> 1)) * 16384 + (cc & 1) * 8192;
    uint32_t d = sb + QBUF(bi);
#pragma unroll
    for (int i = 0; i < 4; i++) {
        int o = (i * 128 + tid) * 16;
        cpa16(d + o, qs + o);
    }
}

__device__ __forceinline__ void p1_expsum(float& ps0, float& ps1, const float (&sa)[4][8]) {
#pragma unroll
    for (int ntp = 0; ntp < 4; ntp++) {
        __half2 e01 = h2exp2(__floats2half2_rn(sa[ntp][0], sa[ntp][1]));
        __half2 e45 = h2exp2(__floats2half2_rn(sa[ntp][4], sa[ntp][5]));
        __half2 a0 = __hadd2(e01, e45);
        ps0 += __low2float(a0) + __high2float(a0);
        __half2 e23 = h2exp2(__floats2half2_rn(sa[ntp][2], sa[ntp][3]));
        __half2 e67 = h2exp2(__floats2half2_rn(sa[ntp][6], sa[ntp][7]));
        __half2 a1 = __hadd2(e23, e67);
        ps1 += __low2float(a1) + __high2float(a1);
    }
}

__device__ __forceinline__ void p1_iter(uint32_t sb, int n, int cc_issue, int bi, int bn,
                                        bool do_issue, bool do_s,
                                        float (&sa)[4][8], float (&sbk)[4][8],
                                        const uint32_t (&ah)[4][4],
                                        float& ps0, float& ps1,
                                        uint32_t t128, const uint32_t (&cx)[4]) {
    CP_WAIT0(); __syncthreads();
    if (do_issue) { p1_issue_q(sb, bi, n, cc_issue); CP_COMMIT(); }
    if (do_s) mma_block(sbk, ah, sb + QBUF(bn), t128, cx);   // tensor: S(j+1)
    p1_expsum(ps0, ps1, sa);                                  // mufu: exp(j), overlaps
}

__global__ void __launch_bounds__(128, 4)
pass1_denom() {
    extern __shared__ char smem[];
    uint32_t sb = smem_u32(smem);
    int tid = threadIdx.x, w = tid >> 5, l = tid & 31;
    int kt = blockIdx.x, qs = blockIdx.y, n = blockIdx.z;

    uint32_t t128 = (uint32_t)(l & 15) * 128;
    uint32_t msk = (uint32_t)(l & 7) << 4;
    uint32_t cx[4];
#pragma unroll
    for (int ks = 0; ks < 4; ks++) cx[ks] = ((uint32_t)(ks * 32 + ((l >> 4) << 4))) ^ msk;

    int c0 = qs * 16;
    {
        const char* ksrc = g_Kb + (size_t)(n * 32 + (kt >> 1)) * 16384 + (kt & 1) * 8192;
#pragma unroll
        for (int i = 0; i < 4; i++) {
            int o = (i * 128 + tid) * 16;
            cpa16(sb + Z1_K + o, ksrc + o);
        }
        p1_issue_q(sb, 0, n, c0); CP_COMMIT();
        p1_issue_q(sb, 1, n, c0 + 1); CP_COMMIT();
        CP_WAIT1(); __syncthreads();
    }

    uint32_t ah[4][4];
#pragma unroll
    for (int ks = 0; ks < 4; ks++) ld4a(ah[ks], sb + Z1_K + w * 2048 + t128 + cx[ks]);

    float sA[4][8], sB[4][8];
    float ps0 = 0.f, ps1 = 0.f;
    mma_block(sA, ah, sb + QBUF(0), t128, cx);   // S(0)

    // j = 0..11 (2 macro-iters of 6); buffers: issue (j+2)%3, next (j+1)%3
#pragma unroll 1
    for (int m = 0; m < 2; m++) {
        int j0 = m * 6;
        p1_iter(sb, n, c0 + j0 + 2, 2, 1, true, true, sA, sB, ah, ps0, ps1, t128, cx);
        p1_iter(sb, n, c0 + j0 + 3, 0, 2, true, true, sB, sA, ah, ps0, ps1, t128, cx);
        p1_iter(sb, n, c0 + j0 + 4, 1, 0, true, true, sA, sB, ah, ps0, ps1, t128, cx);
        p1_iter(sb, n, c0 + j0 + 5, 2, 1, true, true, sB, sA, ah, ps0, ps1, t128, cx);
        p1_iter(sb, n, c0 + j0 + 6, 0, 2, true, true, sA, sB, ah, ps0, ps1, t128, cx);
        p1_iter(sb, n, c0 + j0 + 7, 1, 0, true, true, sB, sA, ah, ps0, ps1, t128, cx);
    }
    // j = 12..15
    p1_iter(sb, n, c0 + 14, 2, 1, true,  true,  sA, sB, ah, ps0, ps1, t128, cx);
    p1_iter(sb, n, c0 + 15, 0, 2, true,  true,  sB, sA, ah, ps0, ps1, t128, cx);
    p1_iter(sb, n, 0,       0, 0, false, true,  sA, sB, ah, ps0, ps1, t128, cx);
    p1_iter(sb, n, 0,       0, 0, false, false, sB, sA, ah, ps0, ps1, t128, cx);

    ps0 += __shfl_xor_sync(0xFFFFFFFFu, ps0, 1);
    ps0 += __shfl_xor_sync(0xFFFFFFFFu, ps0, 2);
    ps1 += __shfl_xor_sync(0xFFFFFFFFu, ps1, 1);
    ps1 += __shfl_xor_sync(0xFFFFFFFFu, ps1, 2);
    if ((l & 3) == 0) {
        int r = l >> 2;
        atomicAdd(&g_denom[n * HW + kt * 64 + w * 16 + r],     ps0);
        atomicAdd(&g_denom[n * HW + kt * 64 + w * 16 + 8 + r], ps1);
    }
}

// ---------------------------------------------------------------------------
// Prep B: Vt = (V/denom)^T, fp16.
// ---------------------------------------------------------------------------
__global__ void __launch_bounds__(128)
prep_v(const float* __restrict__ V) {
    __shared__ char sm[8192];
    int tid = threadIdx.x;
    int s = blockIdx.x, n = blockIdx.y;
    int c = s >> 1, h = s & 1;

    const float* g = V + ((size_t)n * HW + s * 64) * CD;
    const float* dn = g_denom + n * HW + s * 64;
#pragma unroll
    for (int i = 0; i < 8; i++) {
        int lin4 = i * 128 + tid;
        int k  = lin4 >> 4;
        int c4 = (lin4 & 15) * 4;
        float di = __frcp_rn(dn[k]);
        float4 v = *(const float4*)(g + k * CD + c4);
        float vv[4] = {v.x * di, v.y * di, v.z * di, v.w * di};
#pragma unroll
        for (int j = 0; j < 4; j++) {
            unsigned o = (c4 + j) * 128 + k * 2;
            *(__half*)(sm + SW(o)) = __float2half_rn(vv[j]);
        }
    }
    __syncthreads();

    size_t gb = (size_t)(n * 32 + c) * 16384 + h * 8192;
#pragma unroll
    for (int i = 0; i < 4; i++) {
        int o = (i * 128 + tid) * 16;
        *(float4*)(g_Vb + gb + o) = *(const float4*)(sm + o);
    }
}

// ---------------------------------------------------------------------------
// Pass 2: CTA = 64 q rows, 128 threads. 64 k-chunks, triple-buffered KV ring;
// per iter: S(j+1) interleaved with exp(j), then PV(j).
// smem: Q 8KB + 3 x 16KB = 56KB.
// ---------------------------------------------------------------------------
#define Q_OFF 0
#define KVBUF(b) (8192 + (b) * 16384)   /* K 8KB, V at +8192 */
#define P2_SMEM 57344

__device__ __forceinline__ void p2_issue_kv(uint32_t sb, int bi, int n, int cc) {
    int tid = threadIdx.x;
    size_t cb = (size_t)(n * 32 + (cc >> 1)) * 16384 + (cc & 1) * 8192;
    const char* ksrc = g_Kb + cb;
    const char* vsrc = g_Vb + cb;
    uint32_t d = sb + KVBUF(bi);
#pragma unroll
    for (int i = 0; i < 4; i++) {
        int o = (i * 128 + tid) * 16;
        cpa16(d + o,        ksrc + o);
        cpa16(d + 8192 + o, vsrc + o);
    }
}

__device__ __forceinline__ void p2_iter(uint32_t sb, int n, int cc_issue,
                                        int bi, int bn, int bc, bool do_issue, bool do_s,
                                        float (&sa)[4][8], float (&sbk)[4][8],
                                        uint32_t (&ph)[4][4], float (&oacc)[8][4],
                                        const uint32_t (&qh)[4][4],
                                        uint32_t t128, const uint32_t (&cx)[4]) {
    CP_WAIT0(); __syncthreads();
    if (do_issue) { p2_issue_kv(sb, bi, n, cc_issue); CP_COMMIT(); }
    if (do_s) mma_block(sbk, qh, sb + KVBUF(bn), t128, cx);     // tensor: S(j+1)
    exp_block(ph, sa);                                           // mufu: exp(j), overlaps
    pv_block(oacc, ph, sb + KVBUF(bc) + 8192, t128, cx);         // tensor: PV(j)
}

__global__ void __launch_bounds__(128, 3)
pass2_out(float* __restrict__ Out) {
    extern __shared__ char smem[];
    uint32_t sb = smem_u32(smem);
    int tid = threadIdx.x, w = tid >> 5, l = tid & 31;
    int qt = blockIdx.x, n = blockIdx.y;

    uint32_t t128 = (uint32_t)(l & 15) * 128;
    uint32_t msk = (uint32_t)(l & 7) << 4;
    uint32_t cx[4];
#pragma unroll
    for (int ks = 0; ks < 4; ks++) cx[ks] = ((uint32_t)(ks * 32 + ((l >> 4) << 4))) ^ msk;

    {
        const char* qsrc = g_Qb + (size_t)(n * 32 + (qt >> 1)) * 16384 + (qt & 1) * 8192;
#pragma unroll
        for (int i = 0; i < 4; i++) {
            int o = (i * 128 + tid) * 16;
            cpa16(sb + Q_OFF + o, qsrc + o);
        }
        p2_issue_kv(sb, 0, n, 0); CP_COMMIT();
        p2_issue_kv(sb, 1, n, 1); CP_COMMIT();
        CP_WAIT1(); __syncthreads();
    }

    uint32_t qh[4][4];
#pragma unroll
    for (int ks = 0; ks < 4; ks++) ld4a(qh[ks], sb + Q_OFF + w * 2048 + t128 + cx[ks]);

    float oacc[8][4];
#pragma unroll
    for (int i = 0; i < 8; i++)
#pragma unroll
        for (int j = 0; j < 4; j++) oacc[i][j] = 0.f;

    float sA[4][8], sB[4][8];
    uint32_t ph[4][4];
    mma_block(sA, qh, sb + KVBUF(0), t128, cx);   // S(0)

    // j = 0..59: 10 macro-iters of 6 (buf pattern period 6; banks alternate)
#pragma unroll 1
    for (int m = 0; m < 10; m++) {
        int j0 = m * 6;
        p2_iter(sb, n, j0 + 2, 2, 1, 0, true, true, sA, sB, ph, oacc, qh, t128, cx);
        p2_iter(sb, n, j0 + 3, 0, 2, 1, true, true, sB, sA, ph, oacc, qh, t128, cx);
        p2_iter(sb, n, j0 + 4, 1, 0, 2, true, true, sA, sB, ph, oacc, qh, t128, cx);
        p2_iter(sb, n, j0 + 5, 2, 1, 0, true, true, sB, sA, ph, oacc, qh, t128, cx);
        p2_iter(sb, n, j0 + 6, 0, 2, 1, true, true, sA, sB, ph, oacc, qh, t128, cx);
        p2_iter(sb, n, j0 + 7, 1, 0, 2, true, true, sB, sA, ph, oacc, qh, t128, cx);
    }
    // j = 60..63
    p2_iter(sb, n, 62, 2, 1, 0, true,  true,  sA, sB, ph, oacc, qh, t128, cx);
    p2_iter(sb, n, 63, 0, 2, 1, true,  true,  sB, sA, ph, oacc, qh, t128, cx);
    p2_iter(sb, n, 0,  0, 0, 2, false, true,  sA, sB, ph, oacc, qh, t128, cx);
    p2_iter(sb, n, 0,  0, 0, 0, false, false, sB, sA, ph, oacc, qh, t128, cx);

    {
        int qr = qt * 64 + w * 16 + (l >> 2);
        float* o0 = Out + ((size_t)n * HW + qr) * CD;
        float* o1 = o0 + 8 * CD;
#pragma unroll
        for (int nt = 0; nt < 8; nt++) {
            int c0 = nt * 8 + 2 * (l & 3);
            *(float2*)(o0 + c0) = make_float2(oacc[nt][0], oacc[nt][1]);
            *(float2*)(o1 + c0) = make_float2(oacc[nt][2], oacc[nt][3]);
        }
    }
}

// ---------------------------------------------------------------------------
extern "C" void kernel_launch(void* const* d_in, const int* in_sizes, int n_in,
                              void* d_out, int out_size) {
    const float* Q = (const float*)d_in[0];
    const float* K = (const float*)d_in[1];
    const float* V = (const float*)d_in[2];
    float* Out = (float*)d_out;
    const int N = in_sizes[0] / (HW * CD);  // = 4

    cudaFuncSetAttribute(pass1_denom, cudaFuncAttributeMaxDynamicSharedMemorySize, P1_SMEM);
    cudaFuncSetAttribute(pass2_out,   cudaFuncAttributeMaxDynamicSharedMemorySize, P2_SMEM);

    prep_qk<<<dim3(64, N), 128>>>(Q, K);
    pass1_denom<<<dim3(64, 4, N), 128, P1_SMEM>>>();
    prep_v<<<dim3(64, N), 128>>>(V);
    pass2_out<<<dim3(64, N), 128, P2_SMEM>>>(Out);
}